// round 13
// baseline (speedup 1.0000x reference)
#include <cuda_runtime.h>
#include <cuda_bf16.h>
#include <math_constants.h>
#include <cstdint>

#define B_  4
#define H_  16
#define S_  2048
#define DM  1024
#define DK  64
#define M_  (B_*S_)

// ---------------- scratch (device globals; no allocation allowed) ----------
__device__ float g_attn[M_*DM];
__device__ __nv_bfloat16 g_Qhi[M_*DM], g_Qlo[M_*DM];   // head layout, pre-scaled
__device__ __nv_bfloat16 g_Khi[M_*DM], g_Klo[M_*DM];
__device__ __nv_bfloat16 g_Vhi[M_*DM], g_Vlo[M_*DM];

__device__ __forceinline__ uint32_t smem_u32(const void* p) {
    uint32_t a;
    asm("{ .reg .u64 t; cvta.to.shared.u64 t, %1; cvt.u32.u64 %0, t; }"
        : "=r"(a) : "l"(p));
    return a;
}
__device__ __forceinline__ void cp16(uint32_t dst, const void* src) {
    asm volatile("cp.async.cg.shared.global [%0], [%1], 16;"
        :: "r"(dst), "l"(src));
}
#define CP_COMMIT() asm volatile("cp.async.commit_group;" ::: "memory")
#define CP_WAIT(n)  asm volatile("cp.async.wait_group %0;" :: "n"(n) : "memory")

__device__ __forceinline__ void ldsm_x4(uint32_t r[4], uint32_t addr) {
    asm volatile("ldmatrix.sync.aligned.m8n8.x4.shared.b16 {%0,%1,%2,%3}, [%4];"
        : "=r"(r[0]), "=r"(r[1]), "=r"(r[2]), "=r"(r[3]) : "r"(addr));
}
__device__ __forceinline__ void ldsm_x4t(uint32_t r[4], uint32_t addr) {
    asm volatile("ldmatrix.sync.aligned.m8n8.x4.trans.shared.b16 {%0,%1,%2,%3}, [%4];"
        : "=r"(r[0]), "=r"(r[1]), "=r"(r[2]), "=r"(r[3]) : "r"(addr));
}
__device__ __forceinline__ void mma16816(float d[4], const uint32_t a[4],
                                         const uint32_t b[2]) {
    asm volatile(
        "mma.sync.aligned.m16n8k16.row.col.f32.bf16.bf16.f32 "
        "{%0,%1,%2,%3}, {%4,%5,%6,%7}, {%8,%9}, {%0,%1,%2,%3};"
        : "+f"(d[0]), "+f"(d[1]), "+f"(d[2]), "+f"(d[3])
        : "r"(a[0]), "r"(a[1]), "r"(a[2]), "r"(a[3]), "r"(b[0]), "r"(b[1]));
}

__device__ __forceinline__ uint32_t pk_bf2(float x, float y) {
    __nv_bfloat162 h = __floats2bfloat162_rn(x, y);
    return *reinterpret_cast<uint32_t*>(&h);
}
__device__ __forceinline__ void split2(float x, float y,
                                       uint32_t& hi, uint32_t& lo) {
    __nv_bfloat162 h2 = __floats2bfloat162_rn(x, y);
    float2 hf = __bfloat1622float2(h2);
    __nv_bfloat162 l2 = __floats2bfloat162_rn(x - hf.x, y - hf.y);
    hi = *reinterpret_cast<uint32_t*>(&h2);
    lo = *reinterpret_cast<uint32_t*>(&l2);
}
__device__ __forceinline__ void split8(float4 v0, float4 v1,
                                       uint4& hi, uint4& lo) {
    float h[8], f[8] = {v0.x, v0.y, v0.z, v0.w, v1.x, v1.y, v1.z, v1.w};
    float l[8];
    #pragma unroll
    for (int i = 0; i < 8; i++) {
        __nv_bfloat16 hb = __float2bfloat16_rn(f[i]);
        h[i] = __bfloat162float(hb);
        l[i] = f[i] - h[i];
    }
    hi = make_uint4(pk_bf2(h[0],h[1]), pk_bf2(h[2],h[3]),
                    pk_bf2(h[4],h[5]), pk_bf2(h[6],h[7]));
    lo = make_uint4(pk_bf2(l[0],l[1]), pk_bf2(l[2],l[3]),
                    pk_bf2(l[4],l[5]), pk_bf2(l[6],l[7]));
}

// Fast exp2 on FMA pipe (no MUFU).
__device__ __forceinline__ float exp2fast(float x) {
    x = fmaxf(x, -126.0f);
    float z = x + 12582912.0f;
    int   k = __float_as_int(z) - 0x4B400000;
    float f = x - (z - 12582912.0f);
    float p = fmaf(0.00133336f, f, 0.00961813f);
    p = fmaf(p, f, 0.05550411f);
    p = fmaf(p, f, 0.24022651f);
    p = fmaf(p, f, 0.69314718f);
    p = fmaf(p, f, 1.0f);
    return __int_as_float(__float_as_int(p) + (k << 23));
}

extern __shared__ char dynsm[];

// ---------------------------------------------------------------------------
// Tensor-core GEMM body (R10 compute), DOUBLE-BUFFERED smem, ONE sync/chunk.
// Splits of chunk c+1 stored immediately to alternate buffer (regs die before
// the MMA block — no cross-MMA register lifetime, unlike R11's regression).
// ---------------------------------------------------------------------------
#define TSTR   80
#define TILEB  (128*TSTR)
#define GSTG   (4*TILEB)          // one stage: [AHI][ALO][WHI][WLO]
#define GEMM_SMEM (2*GSTG)        // 81920
#define AT_HI  0
#define AT_LO  TILEB
#define WT_HI  (2*TILEB)
#define WT_LO  (3*TILEB)

__device__ __forceinline__ void gemm_body(
    const float* __restrict__ A, const float* __restrict__ W,
    const float* __restrict__ bias, float scale,
    __nv_bfloat16* __restrict__ outhi, __nv_bfloat16* __restrict__ outlo,
    float* __restrict__ outf, int mode)
{
    const uint32_t sb = smem_u32(dynsm);
    const int tid = threadIdx.x;
    const int m0  = blockIdx.y << 7;
    const int n0  = blockIdx.x << 7;
    const int warp = tid >> 5;
    const int lane = tid & 31;
    const int wm = (warp >> 2) * 64;
    const int wn = (warp & 3) * 32;

    const uint32_t arow  = (lane & 15) * TSTR + (lane >> 4) * 16;
    const uint32_t brow4 = (lane & 7) * TSTR + ((lane >> 3) & 1) * 16
                         + (lane >> 4) * (8 * TSTR);

    const int lrow = tid >> 1;
    const int lcg  = (tid & 1) * 16;
    const float* Ag = A + (size_t)(m0 + lrow) * DM + lcg;
    const float* Wg = W + (size_t)(n0 + lrow) * DM + lcg;
    const uint32_t rowoff = lrow * TSTR + lcg * 2;

    float acc[4][4][4];
    #pragma unroll
    for (int i = 0; i < 4; i++)
        #pragma unroll
        for (int j = 0; j < 4; j++)
            #pragma unroll
            for (int r = 0; r < 4; r++) acc[i][j][r] = 0.f;

    // prologue: split chunk 0 into buf0; preload chunk 1 regs
    float4 ra0, ra1, ra2, ra3, rw0, rw1, rw2, rw3;
    {
        ra0 = *(const float4*)(Ag);      ra1 = *(const float4*)(Ag + 4);
        ra2 = *(const float4*)(Ag + 8);  ra3 = *(const float4*)(Ag + 12);
        rw0 = *(const float4*)(Wg);      rw1 = *(const float4*)(Wg + 4);
        rw2 = *(const float4*)(Wg + 8);  rw3 = *(const float4*)(Wg + 12);
        char* s = dynsm + rowoff;
        uint4 hi, lo;
        split8(ra0, ra1, hi, lo);
        *(uint4*)(s + AT_HI)      = hi;  *(uint4*)(s + AT_LO)      = lo;
        split8(ra2, ra3, hi, lo);
        *(uint4*)(s + AT_HI + 16) = hi;  *(uint4*)(s + AT_LO + 16) = lo;
        split8(rw0, rw1, hi, lo);
        *(uint4*)(s + WT_HI)      = hi;  *(uint4*)(s + WT_LO)      = lo;
        split8(rw2, rw3, hi, lo);
        *(uint4*)(s + WT_HI + 16) = hi;  *(uint4*)(s + WT_LO + 16) = lo;
    }
    ra0 = *(const float4*)(Ag + 32);  ra1 = *(const float4*)(Ag + 36);
    ra2 = *(const float4*)(Ag + 40);  ra3 = *(const float4*)(Ag + 44);
    rw0 = *(const float4*)(Wg + 32);  rw1 = *(const float4*)(Wg + 36);
    rw2 = *(const float4*)(Wg + 40);  rw3 = *(const float4*)(Wg + 44);

    for (int c = 0; c < DM / 32; ++c) {
        __syncthreads();   // buf c%2 writes visible; buf (c+1)%2 readers done

        if (c + 1 < DM / 32) {   // split+store chunk c+1 -> alternate buffer
            char* s = dynsm + ((c + 1) & 1) * GSTG + rowoff;
            uint4 hi, lo;
            split8(ra0, ra1, hi, lo);
            *(uint4*)(s + AT_HI)      = hi;  *(uint4*)(s + AT_LO)      = lo;
            split8(ra2, ra3, hi, lo);
            *(uint4*)(s + AT_HI + 16) = hi;  *(uint4*)(s + AT_LO + 16) = lo;
            split8(rw0, rw1, hi, lo);
            *(uint4*)(s + WT_HI)      = hi;  *(uint4*)(s + WT_LO)      = lo;
            split8(rw2, rw3, hi, lo);
            *(uint4*)(s + WT_HI + 16) = hi;  *(uint4*)(s + WT_LO + 16) = lo;
            if (c + 2 < DM / 32) {
                const float* An = Ag + (c + 2) * 32;
                const float* Wn = Wg + (c + 2) * 32;
                ra0 = *(const float4*)(An);      ra1 = *(const float4*)(An + 4);
                ra2 = *(const float4*)(An + 8);  ra3 = *(const float4*)(An + 12);
                rw0 = *(const float4*)(Wn);      rw1 = *(const float4*)(Wn + 4);
                rw2 = *(const float4*)(Wn + 8);  rw3 = *(const float4*)(Wn + 12);
            }
        }

        const uint32_t stg = sb + (c & 1) * GSTG;
        #pragma unroll
        for (int ks = 0; ks < 2; ++ks) {
            uint32_t ah[4][4], al[4][4], bh[2][4], bl[2][4];
            #pragma unroll
            for (int mt = 0; mt < 4; ++mt) {
                const uint32_t ao = (wm + mt*16) * TSTR + ks*32 + arow;
                ldsm_x4(ah[mt], stg + AT_HI + ao);
                ldsm_x4(al[mt], stg + AT_LO + ao);
            }
            #pragma unroll
            for (int np = 0; np < 2; ++np) {
                const uint32_t bo = (wn + np*16) * TSTR + ks*32 + brow4;
                ldsm_x4(bh[np], stg + WT_HI + bo);
                ldsm_x4(bl[np], stg + WT_LO + bo);
            }
            #pragma unroll
            for (int mt = 0; mt < 4; ++mt)
                #pragma unroll
                for (int nt = 0; nt < 4; ++nt) {
                    const uint32_t* bhf = &bh[nt >> 1][(nt & 1) * 2];
                    const uint32_t* blf = &bl[nt >> 1][(nt & 1) * 2];
                    mma16816(acc[mt][nt], ah[mt], bhf);
                    mma16816(acc[mt][nt], al[mt], bhf);
                    mma16816(acc[mt][nt], ah[mt], blf);
                }
        }
    }

    #pragma unroll
    for (int mt = 0; mt < 4; ++mt) {
        #pragma unroll
        for (int nt = 0; nt < 4; ++nt) {
            const int col = n0 + wn + nt*8 + (lane & 3) * 2;
            const float2 bv = *(const float2*)(bias + col);
            #pragma unroll
            for (int half = 0; half < 2; ++half) {
                const int row = m0 + wm + mt*16 + (lane >> 2) + half * 8;
                const float v0 = (acc[mt][nt][2*half]   + bv.x) * scale;
                const float v1 = (acc[mt][nt][2*half+1] + bv.y) * scale;
                if (mode) {     // bf16 hi/lo, split-head layout
                    const int head = col >> 6;
                    const int bi = row >> 11, si = row & (S_ - 1);
                    const size_t idx =
                        (((size_t)(bi * H_ + head)) * S_ + si) * DK + (col & 63);
                    uint32_t h2, l2; split2(v0, v1, h2, l2);
                    *(uint32_t*)(outhi + idx) = h2;
                    *(uint32_t*)(outlo + idx) = l2;
                } else {
                    *(float2*)(outf + (size_t)row * DM + col) =
                        make_float2(v0, v1);
                }
            }
        }
    }
}

// Fused Q/K/V projection: blockIdx.z selects operand set (10.4-wave launch).
__global__ __launch_bounds__(256, 1)
void gemm_qkv(const float* __restrict__ q, const float* __restrict__ k,
              const float* __restrict__ v,
              const float* __restrict__ Wq, const float* __restrict__ Wk,
              const float* __restrict__ Wv,
              const float* __restrict__ bq, const float* __restrict__ bk,
              const float* __restrict__ bv,
              __nv_bfloat16* Qhi, __nv_bfloat16* Qlo,
              __nv_bfloat16* Khi, __nv_bfloat16* Klo,
              __nv_bfloat16* Vhi, __nv_bfloat16* Vlo, float scq)
{
    const int z = blockIdx.z;
    const float* A    = (z == 0) ? q  : (z == 1) ? k  : v;
    const float* W    = (z == 0) ? Wq : (z == 1) ? Wk : Wv;
    const float* bias = (z == 0) ? bq : (z == 1) ? bk : bv;
    const float scale = (z == 0) ? scq : 1.0f;
    __nv_bfloat16* ohi = (z == 0) ? Qhi : (z == 1) ? Khi : Vhi;
    __nv_bfloat16* olo = (z == 0) ? Qlo : (z == 1) ? Klo : Vlo;
    gemm_body(A, W, bias, scale, ohi, olo, nullptr, 1);
}

// Output projection: plain fp32 out.
__global__ __launch_bounds__(256, 1)
void gemm_out(const float* __restrict__ A, const float* __restrict__ W,
              const float* __restrict__ bias, float* __restrict__ out)
{
    gemm_body(A, W, bias, 1.0f, nullptr, nullptr, out, 0);
}

// ---------------------------------------------------------------------------
// Tensor-core flash attention (R11/R12 version, byte-identical — 561us):
// static-max softmax, softmax(kt+1) pipelined against PV(kt), 4-stage KV ring.
// ---------------------------------------------------------------------------
#define ASTR    144
#define Q_HI    0
#define Q_LO    18432
#define QREG    36864
#define SK_HI   0
#define SK_LO   9216
#define SV_HI   18432
#define SV_LO   27648
#define KVSTG   36864
#define NKT     (S_/64)
#define ATTN_SMEM (QREG + 4*KVSTG)   // 184320

__device__ __forceinline__ void attn_kv_issue(
    int kt, uint32_t stb, int row, int q4,
    const __nv_bfloat16* Khi, const __nv_bfloat16* Klo,
    const __nv_bfloat16* Vhi, const __nv_bfloat16* Vlo, size_t bh)
{
    if (kt < NKT) {
        const uint32_t st = stb + (kt & 3) * KVSTG + row * ASTR + q4 * 32;
        const size_t e = bh + (size_t)(kt * 64 + row) * DK + q4 * 16;
        cp16(st + SK_HI, Khi + e);  cp16(st + SK_HI + 16, Khi + e + 8);
        cp16(st + SK_LO, Klo + e);  cp16(st + SK_LO + 16, Klo + e + 8);
        cp16(st + SV_HI, Vhi + e);  cp16(st + SV_HI + 16, Vhi + e + 8);
        cp16(st + SV_LO, Vlo + e);  cp16(st + SV_LO + 16, Vlo + e + 8);
    }
    CP_COMMIT();
}

__global__ __launch_bounds__(256, 1)
void attn_mma(const __nv_bfloat16* __restrict__ Qhi,
              const __nv_bfloat16* __restrict__ Qlo,
              const __nv_bfloat16* __restrict__ Khi,
              const __nv_bfloat16* __restrict__ Klo,
              const __nv_bfloat16* __restrict__ Vhi,
              const __nv_bfloat16* __restrict__ Vlo,
              float* __restrict__ outA)
{
    const uint32_t sb  = smem_u32(dynsm);
    const uint32_t stb = sb + QREG;
    const int tid  = threadIdx.x;
    const int lane = tid & 31;
    const int warp = tid >> 5;
    const int qt = blockIdx.x, h = blockIdx.y, b = blockIdx.z;

    const size_t bh = (size_t)(b * H_ + h) * S_ * DK;

    // ---- Q: cp.async ----
    {
        const int row  = tid >> 1;
        const int half = tid & 1;
        const size_t e = bh + (size_t)(qt * 128 + row) * DK + half * 32;
        const uint32_t st = sb + row * ASTR + half * 64;
        #pragma unroll
        for (int j = 0; j < 4; j++) {
            cp16(st + Q_HI + j*16, Qhi + e + j*8);
            cp16(st + Q_LO + j*16, Qlo + e + j*8);
        }
    }
    CP_COMMIT();

    const int krow = tid >> 2;
    const int kq4  = tid & 3;
    attn_kv_issue(0, stb, krow, kq4, Khi, Klo, Vhi, Vlo, bh);
    attn_kv_issue(1, stb, krow, kq4, Khi, Klo, Vhi, Vlo, bh);
    attn_kv_issue(2, stb, krow, kq4, Khi, Klo, Vhi, Vlo, bh);

    CP_WAIT(3);                 // Q done
    __syncthreads();

    uint32_t qah[4][4], qal[4][4];
    {
        const uint32_t qrow = (warp * 16 + (lane & 15)) * ASTR + (lane >> 4) * 16;
        #pragma unroll
        for (int ks = 0; ks < 4; ++ks) {
            ldsm_x4(qah[ks], sb + Q_HI + qrow + ks * 32);
            ldsm_x4(qal[ks], sb + Q_LO + qrow + ks * 32);
        }
    }

    float l0 = 0.f, l1 = 0.f;
    float o[8][4];
    #pragma unroll
    for (int nf = 0; nf < 8; nf++)
        #pragma unroll
        for (int r = 0; r < 4; r++) o[nf][r] = 0.f;

    const uint32_t kbrow4 = (lane & 7) * ASTR + ((lane >> 3) & 1) * 16
                          + (lane >> 4) * (8 * ASTR);
    const uint32_t vbrow4 = (lane & 15) * ASTR + (lane >> 4) * 16;

    auto scores = [&](int kt1, float (&sacc)[8][4]) {
        const uint32_t kb = stb + (kt1 & 3) * KVSTG;
        #pragma unroll
        for (int nf = 0; nf < 8; nf++)
            #pragma unroll
            for (int r = 0; r < 4; r++) sacc[nf][r] = 0.f;
        #pragma unroll
        for (int ks = 0; ks < 4; ++ks) {
            #pragma unroll
            for (int np = 0; np < 4; ++np) {
                uint32_t bh4[4], bl4[4];
                const uint32_t ko = np * 16 * ASTR + ks * 32 + kbrow4;
                ldsm_x4(bh4, kb + SK_HI + ko);
                ldsm_x4(bl4, kb + SK_LO + ko);
                mma16816(sacc[2*np],   qah[ks], &bh4[0]);
                mma16816(sacc[2*np],   qal[ks], &bh4[0]);
                mma16816(sacc[2*np],   qah[ks], &bl4[0]);
                mma16816(sacc[2*np+1], qah[ks], &bh4[2]);
                mma16816(sacc[2*np+1], qal[ks], &bh4[2]);
                mma16816(sacc[2*np+1], qah[ks], &bl4[2]);
            }
        }
    };
    auto softmax = [&](float (&sacc)[8][4],
                       uint32_t (&phi)[4][4], uint32_t (&plo)[4][4]) {
        #pragma unroll
        for (int nf = 0; nf < 8; nf++) {
            float p0 = exp2fast(sacc[nf][0]);
            float p1 = exp2fast(sacc[nf][1]);
            float p2 = exp2fast(sacc[nf][2]);
            float p3 = exp2fast(sacc[nf][3]);
            l0 += p0 + p1;
            l1 += p2 + p3;
            const int ks = nf >> 1, hf = (nf & 1) * 2;
            split2(p0, p1, phi[ks][hf],     plo[ks][hf]);
            split2(p2, p3, phi[ks][hf + 1], plo[ks][hf + 1]);
        }
    };
    auto pv = [&](int kt, uint32_t (&phi)[4][4], uint32_t (&plo)[4][4]) {
        const uint32_t kb = stb + (kt & 3) * KVSTG;
        #pragma unroll
        for (int ks = 0; ks < 4; ++ks) {
            #pragma unroll
            for (int np = 0; np < 4; ++np) {
                uint32_t vh4[4], vl4[4];
                const uint32_t vo = ks * 16 * ASTR + vbrow4 + np * 32;
                ldsm_x4t(vh4, kb + SV_HI + vo);
                ldsm_x4t(vl4, kb + SV_LO + vo);
                mma16816(o[2*np],   phi[ks], &vh4[0]);
                mma16816(o[2*np],   plo[ks], &vh4[0]);
                mma16816(o[2*np],   phi[ks], &vl4[0]);
                mma16816(o[2*np+1], phi[ks], &vh4[2]);
                mma16816(o[2*np+1], plo[ks], &vh4[2]);
                mma16816(o[2*np+1], phi[ks], &vl4[2]);
            }
        }
    };

    uint32_t P0h[4][4], P0l[4][4], P1h[4][4], P1l[4][4];
    float sacc[8][4];

    CP_WAIT(2);
    __syncthreads();
    scores(0, sacc);
    softmax(sacc, P0h, P0l);

    auto body = [&](int kt,
                    uint32_t (&Pch)[4][4], uint32_t (&Pcl)[4][4],
                    uint32_t (&Pnh)[4][4], uint32_t (&Pnl)[4][4]) {
        CP_WAIT(1);
        __syncthreads();
        attn_kv_issue(kt + 3, stb, krow, kq4, Khi, Klo, Vhi, Vlo, bh);
        scores(kt + 1, sacc);
        softmax(sacc, Pnh, Pnl);
        pv(kt, Pch, Pcl);
    };

    #pragma unroll 1
    for (int k2 = 0; k2 < (NKT - 2) / 2; ++k2) {
        body(2*k2,     P0h, P0l, P1h, P1l);
        body(2*k2 + 1, P1h, P1l, P0h, P0l);
    }
    body(NKT - 2, P0h, P0l, P1h, P1l);
    pv(NKT - 1, P1h, P1l);

    l0 += __shfl_xor_sync(0xffffffffu, l0, 1);
    l0 += __shfl_xor_sync(0xffffffffu, l0, 2);
    l1 += __shfl_xor_sync(0xffffffffu, l1, 1);
    l1 += __shfl_xor_sync(0xffffffffu, l1, 2);

    const float i0 = 1.0f / l0;
    const float i1 = 1.0f / l1;
    const int r0 = qt * 128 + warp * 16 + (lane >> 2);
    #pragma unroll
    for (int nf = 0; nf < 8; nf++) {
        const int col = h * 64 + nf * 8 + (lane & 3) * 2;
        *(float2*)(outA + (size_t)(b * S_ + r0) * DM + col) =
            make_float2(o[nf][0] * i0, o[nf][1] * i0);
        *(float2*)(outA + (size_t)(b * S_ + r0 + 8) * DM + col) =
            make_float2(o[nf][2] * i1, o[nf][3] * i1);
    }
}

// ---------------------------------------------------------------------------
extern "C" void kernel_launch(void* const* d_in, const int* in_sizes, int n_in,
                              void* d_out, int out_size)
{
    const float* q  = (const float*)d_in[0];
    const float* k  = (const float*)d_in[1];
    const float* v  = (const float*)d_in[2];
    const float* Wq = (const float*)d_in[3];
    const float* bq = (const float*)d_in[4];
    const float* Wk = (const float*)d_in[5];
    const float* bk = (const float*)d_in[6];
    const float* Wv = (const float*)d_in[7];
    const float* bv = (const float*)d_in[8];
    const float* Wo = (const float*)d_in[9];
    const float* bo = (const float*)d_in[10];
    float* out = (float*)d_out;

    float* gA;
    __nv_bfloat16 *gQhi, *gQlo, *gKhi, *gKlo, *gVhi, *gVlo;
    cudaGetSymbolAddress((void**)&gA,   g_attn);
    cudaGetSymbolAddress((void**)&gQhi, g_Qhi);
    cudaGetSymbolAddress((void**)&gQlo, g_Qlo);
    cudaGetSymbolAddress((void**)&gKhi, g_Khi);
    cudaGetSymbolAddress((void**)&gKlo, g_Klo);
    cudaGetSymbolAddress((void**)&gVhi, g_Vhi);
    cudaGetSymbolAddress((void**)&gVlo, g_Vlo);

    cudaFuncSetAttribute(gemm_qkv,
        cudaFuncAttributeMaxDynamicSharedMemorySize, GEMM_SMEM);
    cudaFuncSetAttribute(gemm_out,
        cudaFuncAttributeMaxDynamicSharedMemorySize, GEMM_SMEM);
    cudaFuncSetAttribute(attn_mma,
        cudaFuncAttributeMaxDynamicSharedMemorySize, ATTN_SMEM);

    const float SCQ = 0.1803368801f;   // 0.125 * log2(e)

    gemm_qkv<<<dim3(DM/128, M_/128, 3), 256, GEMM_SMEM>>>(
        q, k, v, Wq, Wk, Wv, bq, bk, bv,
        gQhi, gQlo, gKhi, gKlo, gVhi, gVlo, SCQ);
    attn_mma<<<dim3(S_/128, H_, B_), 256, ATTN_SMEM>>>(
        gQhi, gQlo, gKhi, gKlo, gVhi, gVlo, gA);
    gemm_out<<<dim3(DM/128, M_/128), 256, GEMM_SMEM>>>(gA, Wo, bo, out);
}

// round 14
// speedup vs baseline: 1.1108x; 1.1108x over previous
#include <cuda_runtime.h>
#include <cuda_bf16.h>
#include <math_constants.h>
#include <cstdint>

#define B_  4
#define H_  16
#define S_  2048
#define DM  1024
#define DK  64
#define M_  (B_*S_)

// ---------------- scratch (device globals; no allocation allowed) ----------
__device__ float g_attn[M_*DM];
__device__ __nv_bfloat16 g_Qhi[M_*DM], g_Qlo[M_*DM];   // head layout, pre-scaled
__device__ __nv_bfloat16 g_Khi[M_*DM], g_Klo[M_*DM];
__device__ __nv_bfloat16 g_Vhi[M_*DM], g_Vlo[M_*DM];

__device__ __forceinline__ uint32_t smem_u32(const void* p) {
    uint32_t a;
    asm("{ .reg .u64 t; cvta.to.shared.u64 t, %1; cvt.u32.u64 %0, t; }"
        : "=r"(a) : "l"(p));
    return a;
}
__device__ __forceinline__ void cp16(uint32_t dst, const void* src) {
    asm volatile("cp.async.cg.shared.global [%0], [%1], 16;"
        :: "r"(dst), "l"(src));
}
#define CP_COMMIT() asm volatile("cp.async.commit_group;" ::: "memory")
#define CP_WAIT(n)  asm volatile("cp.async.wait_group %0;" :: "n"(n) : "memory")

__device__ __forceinline__ void ldsm_x4(uint32_t r[4], uint32_t addr) {
    asm volatile("ldmatrix.sync.aligned.m8n8.x4.shared.b16 {%0,%1,%2,%3}, [%4];"
        : "=r"(r[0]), "=r"(r[1]), "=r"(r[2]), "=r"(r[3]) : "r"(addr));
}
__device__ __forceinline__ void ldsm_x4t(uint32_t r[4], uint32_t addr) {
    asm volatile("ldmatrix.sync.aligned.m8n8.x4.trans.shared.b16 {%0,%1,%2,%3}, [%4];"
        : "=r"(r[0]), "=r"(r[1]), "=r"(r[2]), "=r"(r[3]) : "r"(addr));
}
__device__ __forceinline__ void mma16816(float d[4], const uint32_t a[4],
                                         const uint32_t b[2]) {
    asm volatile(
        "mma.sync.aligned.m16n8k16.row.col.f32.bf16.bf16.f32 "
        "{%0,%1,%2,%3}, {%4,%5,%6,%7}, {%8,%9}, {%0,%1,%2,%3};"
        : "+f"(d[0]), "+f"(d[1]), "+f"(d[2]), "+f"(d[3])
        : "r"(a[0]), "r"(a[1]), "r"(a[2]), "r"(a[3]), "r"(b[0]), "r"(b[1]));
}

__device__ __forceinline__ uint32_t pk_bf2(float x, float y) {
    __nv_bfloat162 h = __floats2bfloat162_rn(x, y);
    return *reinterpret_cast<uint32_t*>(&h);
}
__device__ __forceinline__ void split2(float x, float y,
                                       uint32_t& hi, uint32_t& lo) {
    __nv_bfloat162 h2 = __floats2bfloat162_rn(x, y);
    float2 hf = __bfloat1622float2(h2);
    __nv_bfloat162 l2 = __floats2bfloat162_rn(x - hf.x, y - hf.y);
    hi = *reinterpret_cast<uint32_t*>(&h2);
    lo = *reinterpret_cast<uint32_t*>(&l2);
}
__device__ __forceinline__ void split8(float4 v0, float4 v1,
                                       uint4& hi, uint4& lo) {
    float h[8], f[8] = {v0.x, v0.y, v0.z, v0.w, v1.x, v1.y, v1.z, v1.w};
    float l[8];
    #pragma unroll
    for (int i = 0; i < 8; i++) {
        __nv_bfloat16 hb = __float2bfloat16_rn(f[i]);
        h[i] = __bfloat162float(hb);
        l[i] = f[i] - h[i];
    }
    hi = make_uint4(pk_bf2(h[0],h[1]), pk_bf2(h[2],h[3]),
                    pk_bf2(h[4],h[5]), pk_bf2(h[6],h[7]));
    lo = make_uint4(pk_bf2(l[0],l[1]), pk_bf2(l[2],l[3]),
                    pk_bf2(l[4],l[5]), pk_bf2(l[6],l[7]));
}

// Fast exp2 on FMA pipe (no MUFU).
__device__ __forceinline__ float exp2fast(float x) {
    x = fmaxf(x, -126.0f);
    float z = x + 12582912.0f;
    int   k = __float_as_int(z) - 0x4B400000;
    float f = x - (z - 12582912.0f);
    float p = fmaf(0.00133336f, f, 0.00961813f);
    p = fmaf(p, f, 0.05550411f);
    p = fmaf(p, f, 0.24022651f);
    p = fmaf(p, f, 0.69314718f);
    p = fmaf(p, f, 1.0f);
    return __int_as_float(__float_as_int(p) + (k << 23));
}

// ---------------------------------------------------------------------------
// Tensor-core GEMM body — R12/R10 version BYTE-IDENTICAL (199us/launch):
// static 40KB smem, two syncs per 32-chunk, splits between the syncs.
// Only the launch shape changes this round (fused z-indexed Q/K/V).
// ---------------------------------------------------------------------------
#define TSTR   80
#define TILEB  (128*TSTR)
#define AT_HI  0
#define AT_LO  TILEB
#define WT_HI  (2*TILEB)
#define WT_LO  (3*TILEB)

__device__ __forceinline__ void gemm_body(
    const float* __restrict__ A, const float* __restrict__ W,
    const float* __restrict__ bias, float scale,
    __nv_bfloat16* __restrict__ outhi, __nv_bfloat16* __restrict__ outlo,
    float* __restrict__ outf, int mode)
{
    __shared__ __align__(16) char sm[4*TILEB];
    const uint32_t sb = smem_u32(sm);

    const int tid = threadIdx.x;
    const int m0  = blockIdx.y << 7;
    const int n0  = blockIdx.x << 7;
    const int warp = tid >> 5;
    const int lane = tid & 31;
    const int wm = (warp >> 2) * 64;
    const int wn = (warp & 3) * 32;

    const uint32_t arow  = (lane & 15) * TSTR + (lane >> 4) * 16;
    const uint32_t brow4 = (lane & 7) * TSTR + ((lane >> 3) & 1) * 16
                         + (lane >> 4) * (8 * TSTR);

    const int lrow = tid >> 1;
    const int lcg  = (tid & 1) * 16;
    const float* Ag = A + (size_t)(m0 + lrow) * DM + lcg;
    const float* Wg = W + (size_t)(n0 + lrow) * DM + lcg;
    char* smArow = sm + lrow * TSTR + lcg * 2;
    char* smWrow = smArow;

    float acc[4][4][4];
    #pragma unroll
    for (int i = 0; i < 4; i++)
        #pragma unroll
        for (int j = 0; j < 4; j++)
            #pragma unroll
            for (int r = 0; r < 4; r++) acc[i][j][r] = 0.f;

    float4 ra0 = *(const float4*)(Ag);      float4 ra1 = *(const float4*)(Ag + 4);
    float4 ra2 = *(const float4*)(Ag + 8);  float4 ra3 = *(const float4*)(Ag + 12);
    float4 rw0 = *(const float4*)(Wg);      float4 rw1 = *(const float4*)(Wg + 4);
    float4 rw2 = *(const float4*)(Wg + 8);  float4 rw3 = *(const float4*)(Wg + 12);

    for (int c = 0; c < DM / 32; ++c) {
        __syncthreads();
        uint4 hi, lo;
        split8(ra0, ra1, hi, lo);
        *(uint4*)(smArow + AT_HI)      = hi;  *(uint4*)(smArow + AT_LO)      = lo;
        split8(ra2, ra3, hi, lo);
        *(uint4*)(smArow + AT_HI + 16) = hi;  *(uint4*)(smArow + AT_LO + 16) = lo;
        split8(rw0, rw1, hi, lo);
        *(uint4*)(smWrow + WT_HI)      = hi;  *(uint4*)(smWrow + WT_LO)      = lo;
        split8(rw2, rw3, hi, lo);
        *(uint4*)(smWrow + WT_HI + 16) = hi;  *(uint4*)(smWrow + WT_LO + 16) = lo;
        __syncthreads();

        if (c < DM / 32 - 1) {
            const float* An = Ag + (c + 1) * 32;
            const float* Wn = Wg + (c + 1) * 32;
            ra0 = *(const float4*)(An);      ra1 = *(const float4*)(An + 4);
            ra2 = *(const float4*)(An + 8);  ra3 = *(const float4*)(An + 12);
            rw0 = *(const float4*)(Wn);      rw1 = *(const float4*)(Wn + 4);
            rw2 = *(const float4*)(Wn + 8);  rw3 = *(const float4*)(Wn + 12);
        }

        #pragma unroll
        for (int ks = 0; ks < 2; ++ks) {
            uint32_t ah[4][4], al[4][4], bh[2][4], bl[2][4];
            #pragma unroll
            for (int mt = 0; mt < 4; ++mt) {
                const uint32_t ao = (wm + mt*16) * TSTR + ks*32 + arow;
                ldsm_x4(ah[mt], sb + AT_HI + ao);
                ldsm_x4(al[mt], sb + AT_LO + ao);
            }
            #pragma unroll
            for (int np = 0; np < 2; ++np) {
                const uint32_t bo = (wn + np*16) * TSTR + ks*32 + brow4;
                ldsm_x4(bh[np], sb + WT_HI + bo);
                ldsm_x4(bl[np], sb + WT_LO + bo);
            }
            #pragma unroll
            for (int mt = 0; mt < 4; ++mt)
                #pragma unroll
                for (int nt = 0; nt < 4; ++nt) {
                    const uint32_t* bhf = &bh[nt >> 1][(nt & 1) * 2];
                    const uint32_t* blf = &bl[nt >> 1][(nt & 1) * 2];
                    mma16816(acc[mt][nt], ah[mt], bhf);
                    mma16816(acc[mt][nt], al[mt], bhf);
                    mma16816(acc[mt][nt], ah[mt], blf);
                }
        }
    }

    #pragma unroll
    for (int mt = 0; mt < 4; ++mt) {
        #pragma unroll
        for (int nt = 0; nt < 4; ++nt) {
            const int col = n0 + wn + nt*8 + (lane & 3) * 2;
            const float2 bv = *(const float2*)(bias + col);
            #pragma unroll
            for (int half = 0; half < 2; ++half) {
                const int row = m0 + wm + mt*16 + (lane >> 2) + half * 8;
                const float v0 = (acc[mt][nt][2*half]   + bv.x) * scale;
                const float v1 = (acc[mt][nt][2*half+1] + bv.y) * scale;
                if (mode) {     // bf16 hi/lo, split-head layout
                    const int head = col >> 6;
                    const int bi = row >> 11, si = row & (S_ - 1);
                    const size_t idx =
                        (((size_t)(bi * H_ + head)) * S_ + si) * DK + (col & 63);
                    uint32_t h2, l2; split2(v0, v1, h2, l2);
                    *(uint32_t*)(outhi + idx) = h2;
                    *(uint32_t*)(outlo + idx) = l2;
                } else {
                    *(float2*)(outf + (size_t)row * DM + col) =
                        make_float2(v0, v1);
                }
            }
        }
    }
}

// Fused Q/K/V projection: blockIdx.z selects operand set (one 10.4-wave launch)
__global__ __launch_bounds__(256)
void gemm_qkv(const float* __restrict__ q, const float* __restrict__ k,
              const float* __restrict__ v,
              const float* __restrict__ Wq, const float* __restrict__ Wk,
              const float* __restrict__ Wv,
              const float* __restrict__ bq, const float* __restrict__ bk,
              const float* __restrict__ bv,
              __nv_bfloat16* Qhi, __nv_bfloat16* Qlo,
              __nv_bfloat16* Khi, __nv_bfloat16* Klo,
              __nv_bfloat16* Vhi, __nv_bfloat16* Vlo, float scq)
{
    const int z = blockIdx.z;
    const float* A    = (z == 0) ? q  : (z == 1) ? k  : v;
    const float* W    = (z == 0) ? Wq : (z == 1) ? Wk : Wv;
    const float* bias = (z == 0) ? bq : (z == 1) ? bk : bv;
    const float scale = (z == 0) ? scq : 1.0f;
    __nv_bfloat16* ohi = (z == 0) ? Qhi : (z == 1) ? Khi : Vhi;
    __nv_bfloat16* olo = (z == 0) ? Qlo : (z == 1) ? Klo : Vlo;
    gemm_body(A, W, bias, scale, ohi, olo, nullptr, 1);
}

// Output projection: plain fp32 out.
__global__ __launch_bounds__(256)
void gemm_out(const float* __restrict__ A, const float* __restrict__ W,
              const float* __restrict__ bias, float* __restrict__ out)
{
    gemm_body(A, W, bias, 1.0f, nullptr, nullptr, out, 0);
}

// ---------------------------------------------------------------------------
// Tensor-core flash attention (R11/R12 version, byte-identical — 561us):
// static-max softmax, softmax(kt+1) pipelined against PV(kt), 4-stage KV ring.
// ---------------------------------------------------------------------------
#define ASTR    144
#define Q_HI    0
#define Q_LO    18432
#define QREG    36864
#define SK_HI   0
#define SK_LO   9216
#define SV_HI   18432
#define SV_LO   27648
#define KVSTG   36864
#define NKT     (S_/64)
#define ATTN_SMEM (QREG + 4*KVSTG)   // 184320

extern __shared__ char dynsm[];

__device__ __forceinline__ void attn_kv_issue(
    int kt, uint32_t stb, int row, int q4,
    const __nv_bfloat16* Khi, const __nv_bfloat16* Klo,
    const __nv_bfloat16* Vhi, const __nv_bfloat16* Vlo, size_t bh)
{
    if (kt < NKT) {
        const uint32_t st = stb + (kt & 3) * KVSTG + row * ASTR + q4 * 32;
        const size_t e = bh + (size_t)(kt * 64 + row) * DK + q4 * 16;
        cp16(st + SK_HI, Khi + e);  cp16(st + SK_HI + 16, Khi + e + 8);
        cp16(st + SK_LO, Klo + e);  cp16(st + SK_LO + 16, Klo + e + 8);
        cp16(st + SV_HI, Vhi + e);  cp16(st + SV_HI + 16, Vhi + e + 8);
        cp16(st + SV_LO, Vlo + e);  cp16(st + SV_LO + 16, Vlo + e + 8);
    }
    CP_COMMIT();
}

__global__ __launch_bounds__(256, 1)
void attn_mma(const __nv_bfloat16* __restrict__ Qhi,
              const __nv_bfloat16* __restrict__ Qlo,
              const __nv_bfloat16* __restrict__ Khi,
              const __nv_bfloat16* __restrict__ Klo,
              const __nv_bfloat16* __restrict__ Vhi,
              const __nv_bfloat16* __restrict__ Vlo,
              float* __restrict__ outA)
{
    const uint32_t sb  = smem_u32(dynsm);
    const uint32_t stb = sb + QREG;
    const int tid  = threadIdx.x;
    const int lane = tid & 31;
    const int warp = tid >> 5;
    const int qt = blockIdx.x, h = blockIdx.y, b = blockIdx.z;

    const size_t bh = (size_t)(b * H_ + h) * S_ * DK;

    // ---- Q: cp.async ----
    {
        const int row  = tid >> 1;
        const int half = tid & 1;
        const size_t e = bh + (size_t)(qt * 128 + row) * DK + half * 32;
        const uint32_t st = sb + row * ASTR + half * 64;
        #pragma unroll
        for (int j = 0; j < 4; j++) {
            cp16(st + Q_HI + j*16, Qhi + e + j*8);
            cp16(st + Q_LO + j*16, Qlo + e + j*8);
        }
    }
    CP_COMMIT();

    const int krow = tid >> 2;
    const int kq4  = tid & 3;
    attn_kv_issue(0, stb, krow, kq4, Khi, Klo, Vhi, Vlo, bh);
    attn_kv_issue(1, stb, krow, kq4, Khi, Klo, Vhi, Vlo, bh);
    attn_kv_issue(2, stb, krow, kq4, Khi, Klo, Vhi, Vlo, bh);

    CP_WAIT(3);                 // Q done
    __syncthreads();

    uint32_t qah[4][4], qal[4][4];
    {
        const uint32_t qrow = (warp * 16 + (lane & 15)) * ASTR + (lane >> 4) * 16;
        #pragma unroll
        for (int ks = 0; ks < 4; ++ks) {
            ldsm_x4(qah[ks], sb + Q_HI + qrow + ks * 32);
            ldsm_x4(qal[ks], sb + Q_LO + qrow + ks * 32);
        }
    }

    float l0 = 0.f, l1 = 0.f;
    float o[8][4];
    #pragma unroll
    for (int nf = 0; nf < 8; nf++)
        #pragma unroll
        for (int r = 0; r < 4; r++) o[nf][r] = 0.f;

    const uint32_t kbrow4 = (lane & 7) * ASTR + ((lane >> 3) & 1) * 16
                          + (lane >> 4) * (8 * ASTR);
    const uint32_t vbrow4 = (lane & 15) * ASTR + (lane >> 4) * 16;

    auto scores = [&](int kt1, float (&sacc)[8][4]) {
        const uint32_t kb = stb + (kt1 & 3) * KVSTG;
        #pragma unroll
        for (int nf = 0; nf < 8; nf++)
            #pragma unroll
            for (int r = 0; r < 4; r++) sacc[nf][r] = 0.f;
        #pragma unroll
        for (int ks = 0; ks < 4; ++ks) {
            #pragma unroll
            for (int np = 0; np < 4; ++np) {
                uint32_t bh4[4], bl4[4];
                const uint32_t ko = np * 16 * ASTR + ks * 32 + kbrow4;
                ldsm_x4(bh4, kb + SK_HI + ko);
                ldsm_x4(bl4, kb + SK_LO + ko);
                mma16816(sacc[2*np],   qah[ks], &bh4[0]);
                mma16816(sacc[2*np],   qal[ks], &bh4[0]);
                mma16816(sacc[2*np],   qah[ks], &bl4[0]);
                mma16816(sacc[2*np+1], qah[ks], &bh4[2]);
                mma16816(sacc[2*np+1], qal[ks], &bh4[2]);
                mma16816(sacc[2*np+1], qah[ks], &bl4[2]);
            }
        }
    };
    auto softmax = [&](float (&sacc)[8][4],
                       uint32_t (&phi)[4][4], uint32_t (&plo)[4][4]) {
        #pragma unroll
        for (int nf = 0; nf < 8; nf++) {
            float p0 = exp2fast(sacc[nf][0]);
            float p1 = exp2fast(sacc[nf][1]);
            float p2 = exp2fast(sacc[nf][2]);
            float p3 = exp2fast(sacc[nf][3]);
            l0 += p0 + p1;
            l1 += p2 + p3;
            const int ks = nf >> 1, hf = (nf & 1) * 2;
            split2(p0, p1, phi[ks][hf],     plo[ks][hf]);
            split2(p2, p3, phi[ks][hf + 1], plo[ks][hf + 1]);
        }
    };
    auto pv = [&](int kt, uint32_t (&phi)[4][4], uint32_t (&plo)[4][4]) {
        const uint32_t kb = stb + (kt & 3) * KVSTG;
        #pragma unroll
        for (int ks = 0; ks < 4; ++ks) {
            #pragma unroll
            for (int np = 0; np < 4; ++np) {
                uint32_t vh4[4], vl4[4];
                const uint32_t vo = ks * 16 * ASTR + vbrow4 + np * 32;
                ldsm_x4t(vh4, kb + SV_HI + vo);
                ldsm_x4t(vl4, kb + SV_LO + vo);
                mma16816(o[2*np],   phi[ks], &vh4[0]);
                mma16816(o[2*np],   plo[ks], &vh4[0]);
                mma16816(o[2*np],   phi[ks], &vl4[0]);
                mma16816(o[2*np+1], phi[ks], &vh4[2]);
                mma16816(o[2*np+1], plo[ks], &vh4[2]);
                mma16816(o[2*np+1], phi[ks], &vl4[2]);
            }
        }
    };

    uint32_t P0h[4][4], P0l[4][4], P1h[4][4], P1l[4][4];
    float sacc[8][4];

    CP_WAIT(2);
    __syncthreads();
    scores(0, sacc);
    softmax(sacc, P0h, P0l);

    auto body = [&](int kt,
                    uint32_t (&Pch)[4][4], uint32_t (&Pcl)[4][4],
                    uint32_t (&Pnh)[4][4], uint32_t (&Pnl)[4][4]) {
        CP_WAIT(1);
        __syncthreads();
        attn_kv_issue(kt + 3, stb, krow, kq4, Khi, Klo, Vhi, Vlo, bh);
        scores(kt + 1, sacc);
        softmax(sacc, Pnh, Pnl);
        pv(kt, Pch, Pcl);
    };

    #pragma unroll 1
    for (int k2 = 0; k2 < (NKT - 2) / 2; ++k2) {
        body(2*k2,     P0h, P0l, P1h, P1l);
        body(2*k2 + 1, P1h, P1l, P0h, P0l);
    }
    body(NKT - 2, P0h, P0l, P1h, P1l);
    pv(NKT - 1, P1h, P1l);

    l0 += __shfl_xor_sync(0xffffffffu, l0, 1);
    l0 += __shfl_xor_sync(0xffffffffu, l0, 2);
    l1 += __shfl_xor_sync(0xffffffffu, l1, 1);
    l1 += __shfl_xor_sync(0xffffffffu, l1, 2);

    const float i0 = 1.0f / l0;
    const float i1 = 1.0f / l1;
    const int r0 = qt * 128 + warp * 16 + (lane >> 2);
    #pragma unroll
    for (int nf = 0; nf < 8; nf++) {
        const int col = h * 64 + nf * 8 + (lane & 3) * 2;
        *(float2*)(outA + (size_t)(b * S_ + r0) * DM + col) =
            make_float2(o[nf][0] * i0, o[nf][1] * i0);
        *(float2*)(outA + (size_t)(b * S_ + r0 + 8) * DM + col) =
            make_float2(o[nf][2] * i1, o[nf][3] * i1);
    }
}

// ---------------------------------------------------------------------------
extern "C" void kernel_launch(void* const* d_in, const int* in_sizes, int n_in,
                              void* d_out, int out_size)
{
    const float* q  = (const float*)d_in[0];
    const float* k  = (const float*)d_in[1];
    const float* v  = (const float*)d_in[2];
    const float* Wq = (const float*)d_in[3];
    const float* bq = (const float*)d_in[4];
    const float* Wk = (const float*)d_in[5];
    const float* bk = (const float*)d_in[6];
    const float* Wv = (const float*)d_in[7];
    const float* bv = (const float*)d_in[8];
    const float* Wo = (const float*)d_in[9];
    const float* bo = (const float*)d_in[10];
    float* out = (float*)d_out;

    float* gA;
    __nv_bfloat16 *gQhi, *gQlo, *gKhi, *gKlo, *gVhi, *gVlo;
    cudaGetSymbolAddress((void**)&gA,   g_attn);
    cudaGetSymbolAddress((void**)&gQhi, g_Qhi);
    cudaGetSymbolAddress((void**)&gQlo, g_Qlo);
    cudaGetSymbolAddress((void**)&gKhi, g_Khi);
    cudaGetSymbolAddress((void**)&gKlo, g_Klo);
    cudaGetSymbolAddress((void**)&gVhi, g_Vhi);
    cudaGetSymbolAddress((void**)&gVlo, g_Vlo);

    cudaFuncSetAttribute(attn_mma,
        cudaFuncAttributeMaxDynamicSharedMemorySize, ATTN_SMEM);

    const float SCQ = 0.1803368801f;   // 0.125 * log2(e)

    gemm_qkv<<<dim3(DM/128, M_/128, 3), 256>>>(
        q, k, v, Wq, Wk, Wv, bq, bk, bv,
        gQhi, gQlo, gKhi, gKlo, gVhi, gVlo, SCQ);
    attn_mma<<<dim3(S_/128, H_, B_), 256, ATTN_SMEM>>>(
        gQhi, gQlo, gKhi, gKlo, gVhi, gVlo, gA);
    gemm_out<<<dim3(DM/128, M_/128), 256>>>(gA, Wo, bo, out);
}